// round 16
// baseline (speedup 1.0000x reference)
#include <cuda_runtime.h>
#include <cstdint>

#define Nn 50000
#define Ee 800000
#define DAv 256
#define DBv 128
#define Hh 256
#define EPSv 1e-5f
#define SLOPEv 0.01f

// ---------------- scratch (static device globals; no allocation) -------------
__device__ float g_TtA[(size_t)Nn * 512];    // [t_ab | t_aa]
__device__ float g_TB1[(size_t)Nn * 512];    // [t_ba | eB]
__device__ float g_TdA[(size_t)Nn * 256];    // eA
__device__ float g_TB2[(size_t)Nn * 512];    // [t2_ba | eB2]
__device__ float g_TtA2[(size_t)Nn * 512];   // [t2_aa | t2_ab]
__device__ float g_TdA2[(size_t)Nn * 256];   // eA2
__device__ float g_aggr[6][(size_t)Nn * 256];
__device__ float g_hA[(size_t)Nn * Hh];
__device__ float g_hB[(size_t)Nn * Hh];
__device__ int g_deg[3][Nn];
__device__ int g_base[3][Nn + 1];
__device__ int g_cursor[3][Nn];
__device__ int g_csr[3][Ee];
// merged weights
__device__ float g_WtA[512 * 256];
__device__ float g_WB1[512 * 128];
__device__ float g_WdA[256 * 256];
__device__ float g_WB2[512 * 256];
__device__ float g_WtA2[512 * 256];
__device__ float g_WdA2[256 * 256];
__device__ float g_biasB1[512];
__device__ float g_biasB2[512];
__device__ float g_bdA[256];
__device__ float g_bdA2[256];
__device__ float g_Wtmp[4][256 * 256];
__device__ float g_btmp[4][256];
__device__ float g_stats[4][2 * Hh];         // per-BN-instance (parallel BNs)
__device__ float g_prm[4][2 * Hh];

// ---------------- mma helpers -------------------------------------------------
__device__ __forceinline__ uint32_t tf32u(float x) {
    uint32_t u;
    asm("cvt.rna.tf32.f32 %0, %1;" : "=r"(u) : "f"(x));
    return u;
}
__device__ __forceinline__ void mma8(float* d, const uint32_t* a,
                                     const uint32_t* b) {
    asm volatile(
        "mma.sync.aligned.m16n8k8.row.col.f32.tf32.tf32.f32 "
        "{%0,%1,%2,%3}, {%4,%5,%6,%7}, {%8,%9}, {%0,%1,%2,%3};"
        : "+f"(d[0]), "+f"(d[1]), "+f"(d[2]), "+f"(d[3])
        : "r"(a[0]), "r"(a[1]), "r"(a[2]), "r"(a[3]), "r"(b[0]), "r"(b[1]));
}

// ---- tensor-core GEMM: C[M x N] = A[M x K] @ W[N x K]^T (+bias), 3xTF32 ----
// 128x128 tile, 8 warps (2x4), warp tile 64x32, K-chunk 32 (R14 — measured best).
#define SROW 133
#define TBUF (32 * SROW)
#define GM_BUF (2 * TBUF)
#define GM_SMEM (2 * GM_BUF * 4)
__global__ void __launch_bounds__(256, 1)
gemm_mma_k(const float* __restrict__ A, const float* __restrict__ W,
           const float* __restrict__ bias, float* __restrict__ C, int M,
           int K) {
    extern __shared__ float sm[];
    int tid = threadIdx.x;
    int wid = tid >> 5;
    int lane = tid & 31;
    int mBase = blockIdx.x * 128;
    int nBase = blockIdx.y * 128;
    int ldc = (int)gridDim.y * 128;
    int warp_m = wid >> 2;
    int warp_n = wid & 3;

    float d[4][4][4];
#pragma unroll
    for (int i = 0; i < 4; i++)
#pragma unroll
        for (int j = 0; j < 4; j++)
#pragma unroll
            for (int q = 0; q < 4; q++) d[i][j][q] = 0.f;

    int lrow = tid >> 2;
    int lcc = (tid & 3) * 8;

    float4 sa[4], sw[4];
    auto gload = [&](int k0) {
#pragma unroll
        for (int h = 0; h < 2; h++) {
            int row = lrow + h * 64;
            int arow = mBase + row;
            if (arow < M) {
                const float* ap = A + (size_t)arow * K + k0 + lcc;
                sa[2 * h] = *(const float4*)ap;
                sa[2 * h + 1] = *(const float4*)(ap + 4);
            } else {
                sa[2 * h] = make_float4(0.f, 0.f, 0.f, 0.f);
                sa[2 * h + 1] = make_float4(0.f, 0.f, 0.f, 0.f);
            }
            const float* wp = W + (size_t)(nBase + row) * K + k0 + lcc;
            sw[2 * h] = *(const float4*)wp;
            sw[2 * h + 1] = *(const float4*)(wp + 4);
        }
    };
    auto sstore = [&](int b) {
        float* As = sm + b * GM_BUF;
        float* Ws = As + TBUF;
#pragma unroll
        for (int h = 0; h < 2; h++) {
            int row = lrow + h * 64;
            const float* a0 = (const float*)&sa[2 * h];
            const float* a1 = (const float*)&sa[2 * h + 1];
            const float* w0 = (const float*)&sw[2 * h];
            const float* w1 = (const float*)&sw[2 * h + 1];
#pragma unroll
            for (int j = 0; j < 4; j++) {
                As[(lcc + j) * SROW + row] = a0[j];
                As[(lcc + 4 + j) * SROW + row] = a1[j];
                Ws[(lcc + j) * SROW + row] = w0[j];
                Ws[(lcc + 4 + j) * SROW + row] = w1[j];
            }
        }
    };

    gload(0);
    sstore(0);
    __syncthreads();

    uint32_t ah[2][4][4], al[2][4][4], bh[2][4][2], bl[2][4][2];
    int fr0 = warp_m * 64 + (lane >> 2);
    int fc0 = warp_n * 32 + (lane >> 2);

    auto ldfrag = [&](const float* As, const float* Ws, int ks, int u) {
        int krow = ks * 8 + (lane & 3);
#pragma unroll
        for (int mf = 0; mf < 4; mf++) {
            int rb = fr0 + mf * 16;
            float v0 = As[krow * SROW + rb];
            float v1 = As[krow * SROW + rb + 8];
            float v2 = As[(krow + 4) * SROW + rb];
            float v3 = As[(krow + 4) * SROW + rb + 8];
            ah[u][mf][0] = tf32u(v0);
            al[u][mf][0] = __float_as_uint(v0 - __uint_as_float(ah[u][mf][0]));
            ah[u][mf][1] = tf32u(v1);
            al[u][mf][1] = __float_as_uint(v1 - __uint_as_float(ah[u][mf][1]));
            ah[u][mf][2] = tf32u(v2);
            al[u][mf][2] = __float_as_uint(v2 - __uint_as_float(ah[u][mf][2]));
            ah[u][mf][3] = tf32u(v3);
            al[u][mf][3] = __float_as_uint(v3 - __uint_as_float(ah[u][mf][3]));
        }
#pragma unroll
        for (int nf = 0; nf < 4; nf++) {
            float v0 = Ws[krow * SROW + fc0 + nf * 8];
            float v1 = Ws[(krow + 4) * SROW + fc0 + nf * 8];
            bh[u][nf][0] = tf32u(v0);
            bl[u][nf][0] = __float_as_uint(v0 - __uint_as_float(bh[u][nf][0]));
            bh[u][nf][1] = tf32u(v1);
            bl[u][nf][1] = __float_as_uint(v1 - __uint_as_float(bh[u][nf][1]));
        }
    };

    int nc = K >> 5;
    for (int c = 0; c < nc; c++) {
        int b = c & 1;
        if (c + 1 < nc) gload((c + 1) * 32);
        const float* As = sm + b * GM_BUF;
        const float* Ws = As + TBUF;
        ldfrag(As, Ws, 0, 0);
#pragma unroll
        for (int ks = 0; ks < 4; ks++) {
            int u = ks & 1;
            if (ks < 3) ldfrag(As, Ws, ks + 1, u ^ 1);
#pragma unroll
            for (int mf = 0; mf < 4; mf++)
#pragma unroll
                for (int nf = 0; nf < 4; nf++)
                    mma8(d[mf][nf], ah[u][mf], bh[u][nf]);
#pragma unroll
            for (int mf = 0; mf < 4; mf++)
#pragma unroll
                for (int nf = 0; nf < 4; nf++)
                    mma8(d[mf][nf], ah[u][mf], bl[u][nf]);
#pragma unroll
            for (int mf = 0; mf < 4; mf++)
#pragma unroll
                for (int nf = 0; nf < 4; nf++)
                    mma8(d[mf][nf], al[u][mf], bh[u][nf]);
        }
        if (c + 1 < nc) sstore((c + 1) & 1);
        __syncthreads();
    }

#pragma unroll
    for (int mf = 0; mf < 4; mf++) {
        int row0 = mBase + warp_m * 64 + mf * 16 + (lane >> 2);
#pragma unroll
        for (int nf = 0; nf < 4; nf++) {
            int col = nBase + warp_n * 32 + nf * 8 + (lane & 3) * 2;
            float b0 = 0.f, b1 = 0.f;
            if (bias) {
                b0 = bias[col];
                b1 = bias[col + 1];
            }
            if (row0 < M) {
                float2 v = make_float2(d[mf][nf][0] + b0, d[mf][nf][1] + b1);
                *(float2*)(C + (size_t)row0 * ldc + col) = v;
            }
            if (row0 + 8 < M) {
                float2 v = make_float2(d[mf][nf][2] + b0, d[mf][nf][3] + b1);
                *(float2*)(C + (size_t)(row0 + 8) * ldc + col) = v;
            }
        }
    }
}

// ---------------- CSR build ---------------------------------------------------

__global__ void hist_k(const int* __restrict__ dst, int* __restrict__ deg) {
    int i = blockIdx.x * blockDim.x + threadIdx.x;
    if (i < Ee) atomicAdd(&deg[dst[i]], 1);
}

#define SCAN_T 1024
__global__ void scan_k(const int* __restrict__ deg_all,
                       int* __restrict__ base_all,
                       int* __restrict__ cur_all) {
    int z = blockIdx.x;
    const int* deg = deg_all + (size_t)z * Nn;
    int* base = base_all + (size_t)z * (Nn + 1);
    int* cur = cur_all + (size_t)z * Nn;
    __shared__ int sb[SCAN_T];
    int tid = threadIdx.x;
    const int CH = (Nn + SCAN_T - 1) / SCAN_T;
    int lo = tid * CH;
    int hi = lo + CH < Nn ? lo + CH : Nn;
    if (lo > Nn) lo = Nn;
    int s = 0;
    for (int i = lo; i < hi; i++) s += deg[i];
    sb[tid] = s;
    __syncthreads();
    for (int d = 1; d < SCAN_T; d <<= 1) {
        int v = (tid >= d) ? sb[tid - d] : 0;
        __syncthreads();
        sb[tid] += v;
        __syncthreads();
    }
    int run = sb[tid] - s;
    for (int i = lo; i < hi; i++) {
        base[i] = run;
        cur[i] = run;
        run += deg[i];
    }
    if (tid == SCAN_T - 1) base[Nn] = run;
}

__global__ void permute_k(const int* __restrict__ src,
                          const int* __restrict__ dst,
                          int* __restrict__ cur, int* __restrict__ csr) {
    int i = blockIdx.x * blockDim.x + threadIdx.x;
    if (i >= Ee) return;
    int d = dst[i];
    int p = atomicAdd(&cur[d], 1);
    csr[p] = src[i];
}

// ---- gather-mean from a strided source block --------------------------------
__global__ void __launch_bounds__(256)
gather_sum_k(const float* __restrict__ t, int ldt, const int* __restrict__ csr,
             const int* __restrict__ base, float* __restrict__ out) {
    int node = blockIdx.x * 4 + (threadIdx.x >> 6);
    int c4 = threadIdx.x & 63;
    if (node >= Nn) return;
    int s0 = __ldg(base + node);
    int s1 = __ldg(base + node + 1);
    float4 acc = make_float4(0.f, 0.f, 0.f, 0.f);
    int i = s0;
    for (; i + 4 <= s1; i += 4) {
        int a0 = __ldg(csr + i), a1 = __ldg(csr + i + 1);
        int a2 = __ldg(csr + i + 2), a3 = __ldg(csr + i + 3);
        float4 v0 = *(const float4*)(t + (size_t)a0 * ldt + c4 * 4);
        float4 v1 = *(const float4*)(t + (size_t)a1 * ldt + c4 * 4);
        float4 v2 = *(const float4*)(t + (size_t)a2 * ldt + c4 * 4);
        float4 v3 = *(const float4*)(t + (size_t)a3 * ldt + c4 * 4);
        acc.x += v0.x + v1.x + v2.x + v3.x;
        acc.y += v0.y + v1.y + v2.y + v3.y;
        acc.z += v0.z + v1.z + v2.z + v3.z;
        acc.w += v0.w + v1.w + v2.w + v3.w;
    }
    for (; i < s1; i++) {
        int a = __ldg(csr + i);
        float4 v = *(const float4*)(t + (size_t)a * ldt + c4 * 4);
        acc.x += v.x; acc.y += v.y; acc.z += v.z; acc.w += v.w;
    }
    float w = 1.0f / fmaxf((float)(s1 - s0), 1.0f);
    acc.x *= w; acc.y *= w; acc.z *= w; acc.w *= w;
    *(float4*)(out + (size_t)node * 256 + c4 * 4) = acc;
}

// ---- batched weight fusion ----
struct FuseWArgs {
    const float* Wupd[12];
    const float* W[12];
    int off[12];
    int dW[12];
    float* out[12];
};
__global__ void fuse_w_all_k(FuseWArgs a) {
    int z = blockIdx.y;
    int o = blockIdx.x;
    int k = threadIdx.x;
    int dW = a.dW[z];
    if (k >= dW) return;
    const float* wrow = a.Wupd[z] + (size_t)o * (2 * Hh) + a.off[z];
    const float* W = a.W[z];
    float s = 0.0f;
#pragma unroll 8
    for (int j = 0; j < Hh; j++) s += wrow[j] * W[(size_t)j * dW + k];
    a.out[z][(size_t)o * dW + k] = s;
}

struct FuseBArgs {
    const float* Wupd[6];
    const float* bdst[6];
    const float* bsrc[6];
    const float* bupd[6];
    float* out[6];
};
__global__ void fuse_bias_all_k(FuseBArgs a) {
    int z = blockIdx.x;
    int o = threadIdx.x;
    const float* wrow = a.Wupd[z] + (size_t)o * (2 * Hh);
    const float* bdst = a.bdst[z];
    const float* bsrc = a.bsrc[z];
    float s = a.bupd[z][o];
#pragma unroll 8
    for (int j = 0; j < Hh; j++) s += wrow[j] * bdst[j] + wrow[Hh + j] * bsrc[j];
    a.out[z][o] = s;
}

__global__ void assemble_k(const float* __restrict__ Wtmp,
                           const float* __restrict__ btmp,
                           float* __restrict__ WdA, float* __restrict__ WdA2,
                           float* __restrict__ bdA, float* __restrict__ bdA2,
                           float* __restrict__ biasB1, float* __restrict__ biasB2) {
    int z = blockIdx.y;
    int i = blockIdx.x * blockDim.x + threadIdx.x;
    const float* a = Wtmp + (size_t)(z * 2) * 65536;
    const float* b = Wtmp + (size_t)(z * 2 + 1) * 65536;
    float* W = z ? WdA2 : WdA;
    if (i < 65536) W[i] = a[i] + b[i];
    if (i < 256) {
        (z ? bdA2 : bdA)[i] = btmp[(z * 2) * 256 + i] + btmp[(z * 2 + 1) * 256 + i];
        (z ? biasB2 : biasB1)[i] = 0.f;
    }
}

// ---- BN (strided x, fused add of 1-2 aggregate buffers) ----
#define ROWS_PER_BLK 256
__global__ void col_stats3_k(const float* __restrict__ x, int ldx,
                             const float* __restrict__ a1,
                             const float* __restrict__ a2, float prescale,
                             float* __restrict__ sums) {
    int c = threadIdx.x;
    int r0 = blockIdx.x * ROWS_PER_BLK;
    int r1 = r0 + ROWS_PER_BLK;
    if (r1 > Nn) r1 = Nn;
    float s = 0.0f, s2 = 0.0f;
    for (int r = r0; r < r1; r++) {
        float v = x[(size_t)r * ldx + c] + a1[(size_t)r * 256 + c];
        if (a2) v += a2[(size_t)r * 256 + c];
        v *= prescale;
        s += v;
        s2 += v * v;
    }
    atomicAdd(&sums[c], s);
    atomicAdd(&sums[Hh + c], s2);
}

__global__ void bn_finalize_k(const float* __restrict__ sums,
                              const float* __restrict__ g,
                              const float* __restrict__ b,
                              float* __restrict__ prm) {
    int c = threadIdx.x;
    float mean = sums[c] / (float)Nn;
    float var = sums[Hh + c] / (float)Nn - mean * mean;
    float sc = g[c] * rsqrtf(var + EPSv);
    prm[c] = sc;
    prm[Hh + c] = b[c] - mean * sc;
}

__global__ void bn_apply3_k(const float* __restrict__ x, int ldx,
                            const float* __restrict__ a1,
                            const float* __restrict__ a2,
                            const float* __restrict__ prm, float prescale,
                            float* __restrict__ y) {
    int i = blockIdx.x * blockDim.x + threadIdx.x;
    if (i >= Nn * (Hh / 4)) return;
    int r = i >> 6;
    int c = (i & 63) * 4;
    float4 v = *(const float4*)(x + (size_t)r * ldx + c);
    float4 g1 = *(const float4*)(a1 + (size_t)r * 256 + c);
    if (a2) {
        float4 g2 = *(const float4*)(a2 + (size_t)r * 256 + c);
        v.x += g2.x; v.y += g2.y; v.z += g2.z; v.w += g2.w;
    }
    float4 sc = *(const float4*)(prm + c);
    float4 sh = *(const float4*)(prm + Hh + c);
    float t0 = (v.x + g1.x) * prescale * sc.x + sh.x;
    float t1 = (v.y + g1.y) * prescale * sc.y + sh.y;
    float t2 = (v.z + g1.z) * prescale * sc.z + sh.z;
    float t3 = (v.w + g1.w) * prescale * sc.w + sh.w;
    float4 r4;
    r4.x = t0 >= 0.f ? t0 : SLOPEv * t0;
    r4.y = t1 >= 0.f ? t1 : SLOPEv * t1;
    r4.z = t2 >= 0.f ? t2 : SLOPEv * t2;
    r4.w = t3 >= 0.f ? t3 : SLOPEv * t3;
    *(float4*)(y + (size_t)r * 256 + c) = r4;
}

// ---------------- host orchestration ----------------------------------------

static void run_gemm(cudaStream_t st, const float* A, const float* W,
                     const float* bias, float* C, int M, int K, int N) {
    dim3 grid((M + 127) / 128, N / 128);
    gemm_mma_k<<<grid, 256, GM_SMEM, st>>>(A, W, bias, C, M, K);
}

static void run_gather(cudaStream_t st, const float* t, int ldt, const int* csr,
                       const int* base, float* out) {
    gather_sum_k<<<(Nn + 3) / 4, 256, 0, st>>>(t, ldt, csr, base, out);
}

static void run_bn(cudaStream_t st, const float* x, int ldx, const float* a1,
                   const float* a2, float prescale, const float* g,
                   const float* b, float* y, float* stats, float* prm) {
    cudaMemsetAsync(stats, 0, 2 * Hh * sizeof(float), st);
    col_stats3_k<<<(Nn + ROWS_PER_BLK - 1) / ROWS_PER_BLK, Hh, 0, st>>>(x, ldx, a1, a2, prescale, stats);
    bn_finalize_k<<<1, Hh, 0, st>>>(stats, g, b, prm);
    bn_apply3_k<<<(Nn * (Hh / 4) + 255) / 256, 256, 0, st>>>(x, ldx, a1, a2, prm, prescale, y);
}

extern "C" void kernel_launch(void* const* d_in, const int* in_sizes, int n_in,
                              void* d_out, int out_size) {
    const float* x_A = (const float*)d_in[0];
    const float* x_B = (const float*)d_in[1];
    const int* e_ab = (const int*)d_in[2];
    const int* e_ba = (const int*)d_in[3];
    const int* e_aa = (const int*)d_in[4];
    const float* ab_Wsrc1 = (const float*)d_in[5];
    const float* ab_bsrc1 = (const float*)d_in[6];
    const float* ab_Wdst1 = (const float*)d_in[7];
    const float* ab_bdst1 = (const float*)d_in[8];
    const float* ab_Wupd1 = (const float*)d_in[9];
    const float* ab_bupd1 = (const float*)d_in[10];
    const float* ba_Wsrc1 = (const float*)d_in[11];
    const float* ba_bsrc1 = (const float*)d_in[12];
    const float* ba_Wdst1 = (const float*)d_in[13];
    const float* ba_bdst1 = (const float*)d_in[14];
    const float* ba_Wupd1 = (const float*)d_in[15];
    const float* ba_bupd1 = (const float*)d_in[16];
    const float* aa_Wsrc1 = (const float*)d_in[17];
    const float* aa_bsrc1 = (const float*)d_in[18];
    const float* aa_Wdst1 = (const float*)d_in[19];
    const float* aa_bdst1 = (const float*)d_in[20];
    const float* aa_Wupd1 = (const float*)d_in[21];
    const float* aa_bupd1 = (const float*)d_in[22];
    const float* Wsrc2 = (const float*)d_in[23];
    const float* bsrc2 = (const float*)d_in[24];
    const float* Wdst2 = (const float*)d_in[25];
    const float* bdst2 = (const float*)d_in[26];
    const float* Wupd2 = (const float*)d_in[27];
    const float* bupd2 = (const float*)d_in[28];
    const float* bn_g = (const float*)d_in[29];
    const float* bn_b = (const float*)d_in[30];
    float* out = (float*)d_out;

    float *TtA, *TB1, *TdA, *TB2, *TtA2, *TdA2, *aggr, *hA, *hB;
    float *WtA, *WB1, *WdA, *WB2, *WtA2, *WdA2;
    float *biasB1, *biasB2, *bdA, *bdA2, *Wtmp, *btmp, *stats, *prm;
    int *deg, *base, *cursor, *csr;
    cudaGetSymbolAddress((void**)&TtA, g_TtA);
    cudaGetSymbolAddress((void**)&TB1, g_TB1);
    cudaGetSymbolAddress((void**)&TdA, g_TdA);
    cudaGetSymbolAddress((void**)&TB2, g_TB2);
    cudaGetSymbolAddress((void**)&TtA2, g_TtA2);
    cudaGetSymbolAddress((void**)&TdA2, g_TdA2);
    cudaGetSymbolAddress((void**)&aggr, g_aggr);
    cudaGetSymbolAddress((void**)&hA, g_hA);
    cudaGetSymbolAddress((void**)&hB, g_hB);
    cudaGetSymbolAddress((void**)&WtA, g_WtA);
    cudaGetSymbolAddress((void**)&WB1, g_WB1);
    cudaGetSymbolAddress((void**)&WdA, g_WdA);
    cudaGetSymbolAddress((void**)&WB2, g_WB2);
    cudaGetSymbolAddress((void**)&WtA2, g_WtA2);
    cudaGetSymbolAddress((void**)&WdA2, g_WdA2);
    cudaGetSymbolAddress((void**)&biasB1, g_biasB1);
    cudaGetSymbolAddress((void**)&biasB2, g_biasB2);
    cudaGetSymbolAddress((void**)&bdA, g_bdA);
    cudaGetSymbolAddress((void**)&bdA2, g_bdA2);
    cudaGetSymbolAddress((void**)&Wtmp, g_Wtmp);
    cudaGetSymbolAddress((void**)&btmp, g_btmp);
    cudaGetSymbolAddress((void**)&stats, g_stats);
    cudaGetSymbolAddress((void**)&prm, g_prm);
    cudaGetSymbolAddress((void**)&deg, g_deg);
    cudaGetSymbolAddress((void**)&base, g_base);
    cudaGetSymbolAddress((void**)&cursor, g_cursor);
    cudaGetSymbolAddress((void**)&csr, g_csr);

#define AGGR(i) (aggr + (size_t)(i) * Nn * 256)
#define BASE(z) (base + (size_t)(z) * (Nn + 1))
#define CUR(z) (cursor + (size_t)(z) * Nn)
#define CSR(z) (csr + (size_t)(z) * Ee)
#define STATS(i) (stats + (size_t)(i) * 2 * Hh)
#define PRM(i) (prm + (size_t)(i) * 2 * Hh)

    static cudaStream_t s1 = nullptr, s2 = nullptr;
    static cudaEvent_t evFork, evFuse, evCSR, evTA, evB1g, evA1a, evA1b,
        evTA2, evA2a, evA2b, evB2g, evDone;
    if (!s1) {
        cudaStreamCreateWithFlags(&s1, cudaStreamNonBlocking);
        cudaStreamCreateWithFlags(&s2, cudaStreamNonBlocking);
        cudaEvent_t* evs[] = {&evFork, &evFuse, &evCSR, &evTA, &evB1g, &evA1a,
                              &evA1b, &evTA2, &evA2a, &evA2b, &evB2g, &evDone};
        for (auto e : evs) cudaEventCreateWithFlags(e, cudaEventDisableTiming);
        cudaFuncSetAttribute(gemm_mma_k,
                             cudaFuncAttributeMaxDynamicSharedMemorySize,
                             GM_SMEM);
    }
    cudaStream_t s0 = 0;

    cudaEventRecord(evFork, s0);
    cudaStreamWaitEvent(s1, evFork, 0);
    cudaStreamWaitEvent(s2, evFork, 0);

    // ===== s0: weight fusion into merged buffers ===========================
    {
        FuseWArgs fw;
        const float* wu2[3] = {Wupd2 + 0 * (size_t)Hh * 2 * Hh,
                               Wupd2 + 1 * (size_t)Hh * 2 * Hh,
                               Wupd2 + 2 * (size_t)Hh * 2 * Hh};
        fw.Wupd[0] = ab_Wupd1; fw.W[0] = ab_Wsrc1; fw.off[0] = Hh; fw.dW[0] = DAv; fw.out[0] = WtA;
        fw.Wupd[1] = aa_Wupd1; fw.W[1] = aa_Wsrc1; fw.off[1] = Hh; fw.dW[1] = DAv; fw.out[1] = WtA + 256 * 256;
        fw.Wupd[2] = ba_Wupd1; fw.W[2] = ba_Wsrc1; fw.off[2] = Hh; fw.dW[2] = DBv; fw.out[2] = WB1;
        fw.Wupd[3] = ab_Wupd1; fw.W[3] = ab_Wdst1; fw.off[3] = 0;  fw.dW[3] = DBv; fw.out[3] = WB1 + 256 * 128;
        fw.Wupd[4] = ba_Wupd1; fw.W[4] = ba_Wdst1; fw.off[4] = 0; fw.dW[4] = DAv; fw.out[4] = Wtmp + 0 * 65536;
        fw.Wupd[5] = aa_Wupd1; fw.W[5] = aa_Wdst1; fw.off[5] = 0; fw.dW[5] = DAv; fw.out[5] = Wtmp + 1 * 65536;
        fw.Wupd[6] = wu2[1]; fw.W[6] = Wsrc2 + 1 * (size_t)Hh * Hh; fw.off[6] = Hh; fw.dW[6] = Hh; fw.out[6] = WB2;
        fw.Wupd[7] = wu2[0]; fw.W[7] = Wdst2 + 0 * (size_t)Hh * Hh; fw.off[7] = 0;  fw.dW[7] = Hh; fw.out[7] = WB2 + 256 * 256;
        fw.Wupd[8] = wu2[2]; fw.W[8] = Wsrc2 + 2 * (size_t)Hh * Hh; fw.off[8] = Hh; fw.dW[8] = Hh; fw.out[8] = WtA2;
        fw.Wupd[9] = wu2[0]; fw.W[9] = Wsrc2 + 0 * (size_t)Hh * Hh; fw.off[9] = Hh; fw.dW[9] = Hh; fw.out[9] = WtA2 + 256 * 256;
        fw.Wupd[10] = wu2[1]; fw.W[10] = Wdst2 + 1 * (size_t)Hh * Hh; fw.off[10] = 0; fw.dW[10] = Hh; fw.out[10] = Wtmp + 2 * 65536;
        fw.Wupd[11] = wu2[2]; fw.W[11] = Wdst2 + 2 * (size_t)Hh * Hh; fw.off[11] = 0; fw.dW[11] = Hh; fw.out[11] = Wtmp + 3 * 65536;
        fuse_w_all_k<<<dim3(Hh, 12), 256, 0, s0>>>(fw);

        FuseBArgs fb;
        fb.Wupd[0] = ab_Wupd1; fb.bdst[0] = ab_bdst1; fb.bsrc[0] = ab_bsrc1; fb.bupd[0] = ab_bupd1; fb.out[0] = biasB1 + 256;
        fb.Wupd[1] = ba_Wupd1; fb.bdst[1] = ba_bdst1; fb.bsrc[1] = ba_bsrc1; fb.bupd[1] = ba_bupd1; fb.out[1] = btmp + 0 * 256;
        fb.Wupd[2] = aa_Wupd1; fb.bdst[2] = aa_bdst1; fb.bsrc[2] = aa_bsrc1; fb.bupd[2] = aa_bupd1; fb.out[2] = btmp + 1 * 256;
        fb.Wupd[3] = wu2[0]; fb.bdst[3] = bdst2 + 0 * Hh; fb.bsrc[3] = bsrc2 + 0 * Hh; fb.bupd[3] = bupd2 + 0 * Hh; fb.out[3] = biasB2 + 256;
        fb.Wupd[4] = wu2[1]; fb.bdst[4] = bdst2 + 1 * Hh; fb.bsrc[4] = bsrc2 + 1 * Hh; fb.bupd[4] = bupd2 + 1 * Hh; fb.out[4] = btmp + 2 * 256;
        fb.Wupd[5] = wu2[2]; fb.bdst[5] = bdst2 + 2 * Hh; fb.bsrc[5] = bsrc2 + 2 * Hh; fb.bupd[5] = bupd2 + 2 * Hh; fb.out[5] = btmp + 3 * 256;
        fuse_bias_all_k<<<6, Hh, 0, s0>>>(fb);
        assemble_k<<<dim3(256, 2), 256, 0, s0>>>(Wtmp, btmp, WdA, WdA2, bdA,
                                                 bdA2, biasB1, biasB2);
    }
    cudaEventRecord(evFuse, s0);

    // ===== s0: x_A family ==================================================
    run_gemm(s0, x_A, WtA, nullptr, TtA, Nn, DAv, 512);   // [t_ab | t_aa]
    cudaEventRecord(evTA, s0);
    run_gemm(s0, x_A, WdA, bdA, TdA, Nn, DAv, 256);       // eA

    // ===== s1: x_B family right after fuse =================================
    cudaStreamWaitEvent(s1, evFuse, 0);
    run_gemm(s1, x_B, WB1, biasB1, TB1, Nn, DBv, 512);    // [t_ba | eB]

    // ===== s2: CSR build (concurrent with GEMMs) ===========================
    cudaMemsetAsync(deg, 0, 3 * Nn * sizeof(int), s2);
    hist_k<<<(Ee + 255) / 256, 256, 0, s2>>>(e_ab + Ee, deg + 0 * Nn);
    hist_k<<<(Ee + 255) / 256, 256, 0, s2>>>(e_ba + Ee, deg + 1 * Nn);
    hist_k<<<(Ee + 255) / 256, 256, 0, s2>>>(e_aa + Ee, deg + 2 * Nn);
    scan_k<<<3, SCAN_T, 0, s2>>>(deg, base, cursor);
    permute_k<<<(Ee + 255) / 256, 256, 0, s2>>>(e_ab, e_ab + Ee, CUR(0), CSR(0));
    permute_k<<<(Ee + 255) / 256, 256, 0, s2>>>(e_ba, e_ba + Ee, CUR(1), CSR(1));
    permute_k<<<(Ee + 255) / 256, 256, 0, s2>>>(e_aa, e_aa + Ee, CUR(2), CSR(2));
    cudaEventRecord(evCSR, s2);

    // ===== layer-1 gathers =================================================
    // s1: aA1a (t_ba from TB1 — own stream order) after CSR
    cudaStreamWaitEvent(s1, evCSR, 0);
    run_gather(s1, TB1, 512, CSR(1), BASE(1), AGGR(1));   // aA1a
    cudaEventRecord(evA1a, s1);
    // s2: aB1 (t_ab) then aA1b (t_aa), both from TtA
    cudaStreamWaitEvent(s2, evTA, 0);
    run_gather(s2, TtA, 512, CSR(0), BASE(0), AGGR(0));   // aB1
    cudaEventRecord(evB1g, s2);
    run_gather(s2, TtA + 256, 512, CSR(2), BASE(2), AGGR(2));  // aA1b
    cudaEventRecord(evA1b, s2);

    // ===== s1: BN_B1 -> hB, then hB family (stays on s1) ===================
    cudaStreamWaitEvent(s1, evB1g, 0);
    run_bn(s1, TB1 + 256, 512, AGGR(0), nullptr, 1.0f, bn_g + 1 * Hh,
           bn_b + 1 * Hh, hB, STATS(0), PRM(0));
    run_gemm(s1, hB, WB2, biasB2, TB2, Nn, Hh, 512);      // [t2_ba | eB2]
    run_gather(s1, TB2, 512, CSR(1), BASE(1), AGGR(3));   // aA2a (t2_ba)
    cudaEventRecord(evA2a, s1);

    // ===== s0: BN_A1 -> hA; hA family ======================================
    cudaStreamWaitEvent(s0, evA1a, 0);
    cudaStreamWaitEvent(s0, evA1b, 0);
    run_bn(s0, TdA, 256, AGGR(1), AGGR(2), 0.5f, bn_g + 0 * Hh, bn_b + 0 * Hh,
           hA, STATS(1), PRM(1));
    run_gemm(s0, hA, WtA2, nullptr, TtA2, Nn, Hh, 512);   // [t2_aa | t2_ab]
    cudaEventRecord(evTA2, s0);
    run_gemm(s0, hA, WdA2, bdA2, TdA2, Nn, Hh, 256);      // eA2

    // ===== s2: layer-2 gathers from TtA2 ===================================
    cudaStreamWaitEvent(s2, evTA2, 0);
    run_gather(s2, TtA2, 512, CSR(2), BASE(2), AGGR(4));  // aA2b (t2_aa)
    cudaEventRecord(evA2b, s2);
    run_gather(s2, TtA2 + 256, 512, CSR(0), BASE(0), AGGR(5));  // aB2 (t2_ab)
    cudaEventRecord(evB2g, s2);

    // ===== output BNs in parallel: outA on s0, outB on s1 ==================
    cudaStreamWaitEvent(s0, evA2a, 0);
    cudaStreamWaitEvent(s0, evA2b, 0);
    run_bn(s0, TdA2, 256, AGGR(3), AGGR(4), 0.5f, bn_g + 2 * Hh, bn_b + 2 * Hh,
           out, STATS(2), PRM(2));
    cudaStreamWaitEvent(s1, evB2g, 0);
    run_bn(s1, TB2 + 256, 512, AGGR(5), nullptr, 1.0f, bn_g + 3 * Hh,
           bn_b + 3 * Hh, out + (size_t)Nn * Hh, STATS(3), PRM(3));
    cudaEventRecord(evDone, s1);
    cudaStreamWaitEvent(s0, evDone, 0);
}

// round 17
// speedup vs baseline: 1.4168x; 1.4168x over previous
#include <cuda_runtime.h>
#include <cstdint>

#define Nn 50000
#define Ee 800000
#define DAv 256
#define DBv 128
#define Hh 256
#define EPSv 1e-5f
#define SLOPEv 0.01f

// ---------------- scratch (static device globals; no allocation) -------------
__device__ float g_TtA[(size_t)Nn * 512];    // [t_ab | t_aa]
__device__ float g_TB1[(size_t)Nn * 512];    // [t_ba | eB]
__device__ float g_TdA[(size_t)Nn * 256];    // eA
__device__ float g_TB2[(size_t)Nn * 512];    // [t2_ba | eB2]
__device__ float g_TtA2[(size_t)Nn * 512];   // [t2_aa | t2_ab]
__device__ float g_TdA2[(size_t)Nn * 256];   // eA2
__device__ float g_aggr[6][(size_t)Nn * 256];
__device__ float g_hA[(size_t)Nn * Hh];
__device__ float g_hB[(size_t)Nn * Hh];
__device__ int g_deg[3][Nn];
__device__ int g_base[3][Nn + 1];
__device__ int g_cursor[3][Nn];
__device__ int g_csr[3][Ee];
// merged weights
__device__ float g_WtA[512 * 256];
__device__ float g_WB1[512 * 128];
__device__ float g_WdA[256 * 256];
__device__ float g_WB2[512 * 256];
__device__ float g_WtA2[512 * 256];
__device__ float g_WdA2[256 * 256];
__device__ float g_biasB1[512];
__device__ float g_biasB2[512];
__device__ float g_bdA[256];
__device__ float g_bdA2[256];
__device__ float g_Wtmp[4][256 * 256];
__device__ float g_btmp[4][256];
__device__ float g_stats[2][2 * Hh];         // separate for the 2 parallel tail BNs
__device__ float g_prm[2][2 * Hh];

// ---------------- mma helpers -------------------------------------------------
__device__ __forceinline__ uint32_t tf32u(float x) {
    uint32_t u;
    asm("cvt.rna.tf32.f32 %0, %1;" : "=r"(u) : "f"(x));
    return u;
}
__device__ __forceinline__ void mma8(float* d, const uint32_t* a,
                                     const uint32_t* b) {
    asm volatile(
        "mma.sync.aligned.m16n8k8.row.col.f32.tf32.tf32.f32 "
        "{%0,%1,%2,%3}, {%4,%5,%6,%7}, {%8,%9}, {%0,%1,%2,%3};"
        : "+f"(d[0]), "+f"(d[1]), "+f"(d[2]), "+f"(d[3])
        : "r"(a[0]), "r"(a[1]), "r"(a[2]), "r"(a[3]), "r"(b[0]), "r"(b[1]));
}

// ---- tensor-core GEMM: C[M x N] = A[M x K] @ W[N x K]^T (+bias), 3xTF32 ----
// 128x128 tile, 8 warps (2x4), warp tile 64x32, K-chunk 32 (R14 — measured best).
#define SROW 133
#define TBUF (32 * SROW)
#define GM_BUF (2 * TBUF)
#define GM_SMEM (2 * GM_BUF * 4)
__global__ void __launch_bounds__(256, 1)
gemm_mma_k(const float* __restrict__ A, const float* __restrict__ W,
           const float* __restrict__ bias, float* __restrict__ C, int M,
           int K) {
    extern __shared__ float sm[];
    int tid = threadIdx.x;
    int wid = tid >> 5;
    int lane = tid & 31;
    int mBase = blockIdx.x * 128;
    int nBase = blockIdx.y * 128;
    int ldc = (int)gridDim.y * 128;
    int warp_m = wid >> 2;
    int warp_n = wid & 3;

    float d[4][4][4];
#pragma unroll
    for (int i = 0; i < 4; i++)
#pragma unroll
        for (int j = 0; j < 4; j++)
#pragma unroll
            for (int q = 0; q < 4; q++) d[i][j][q] = 0.f;

    int lrow = tid >> 2;
    int lcc = (tid & 3) * 8;

    float4 sa[4], sw[4];
    auto gload = [&](int k0) {
#pragma unroll
        for (int h = 0; h < 2; h++) {
            int row = lrow + h * 64;
            int arow = mBase + row;
            if (arow < M) {
                const float* ap = A + (size_t)arow * K + k0 + lcc;
                sa[2 * h] = *(const float4*)ap;
                sa[2 * h + 1] = *(const float4*)(ap + 4);
            } else {
                sa[2 * h] = make_float4(0.f, 0.f, 0.f, 0.f);
                sa[2 * h + 1] = make_float4(0.f, 0.f, 0.f, 0.f);
            }
            const float* wp = W + (size_t)(nBase + row) * K + k0 + lcc;
            sw[2 * h] = *(const float4*)wp;
            sw[2 * h + 1] = *(const float4*)(wp + 4);
        }
    };
    auto sstore = [&](int b) {
        float* As = sm + b * GM_BUF;
        float* Ws = As + TBUF;
#pragma unroll
        for (int h = 0; h < 2; h++) {
            int row = lrow + h * 64;
            const float* a0 = (const float*)&sa[2 * h];
            const float* a1 = (const float*)&sa[2 * h + 1];
            const float* w0 = (const float*)&sw[2 * h];
            const float* w1 = (const float*)&sw[2 * h + 1];
#pragma unroll
            for (int j = 0; j < 4; j++) {
                As[(lcc + j) * SROW + row] = a0[j];
                As[(lcc + 4 + j) * SROW + row] = a1[j];
                Ws[(lcc + j) * SROW + row] = w0[j];
                Ws[(lcc + 4 + j) * SROW + row] = w1[j];
            }
        }
    };

    gload(0);
    sstore(0);
    __syncthreads();

    uint32_t ah[2][4][4], al[2][4][4], bh[2][4][2], bl[2][4][2];
    int fr0 = warp_m * 64 + (lane >> 2);
    int fc0 = warp_n * 32 + (lane >> 2);

    auto ldfrag = [&](const float* As, const float* Ws, int ks, int u) {
        int krow = ks * 8 + (lane & 3);
#pragma unroll
        for (int mf = 0; mf < 4; mf++) {
            int rb = fr0 + mf * 16;
            float v0 = As[krow * SROW + rb];
            float v1 = As[krow * SROW + rb + 8];
            float v2 = As[(krow + 4) * SROW + rb];
            float v3 = As[(krow + 4) * SROW + rb + 8];
            ah[u][mf][0] = tf32u(v0);
            al[u][mf][0] = __float_as_uint(v0 - __uint_as_float(ah[u][mf][0]));
            ah[u][mf][1] = tf32u(v1);
            al[u][mf][1] = __float_as_uint(v1 - __uint_as_float(ah[u][mf][1]));
            ah[u][mf][2] = tf32u(v2);
            al[u][mf][2] = __float_as_uint(v2 - __uint_as_float(ah[u][mf][2]));
            ah[u][mf][3] = tf32u(v3);
            al[u][mf][3] = __float_as_uint(v3 - __uint_as_float(ah[u][mf][3]));
        }
#pragma unroll
        for (int nf = 0; nf < 4; nf++) {
            float v0 = Ws[krow * SROW + fc0 + nf * 8];
            float v1 = Ws[(krow + 4) * SROW + fc0 + nf * 8];
            bh[u][nf][0] = tf32u(v0);
            bl[u][nf][0] = __float_as_uint(v0 - __uint_as_float(bh[u][nf][0]));
            bh[u][nf][1] = tf32u(v1);
            bl[u][nf][1] = __float_as_uint(v1 - __uint_as_float(bh[u][nf][1]));
        }
    };

    int nc = K >> 5;
    for (int c = 0; c < nc; c++) {
        int b = c & 1;
        if (c + 1 < nc) gload((c + 1) * 32);
        const float* As = sm + b * GM_BUF;
        const float* Ws = As + TBUF;
        ldfrag(As, Ws, 0, 0);
#pragma unroll
        for (int ks = 0; ks < 4; ks++) {
            int u = ks & 1;
            if (ks < 3) ldfrag(As, Ws, ks + 1, u ^ 1);
#pragma unroll
            for (int mf = 0; mf < 4; mf++)
#pragma unroll
                for (int nf = 0; nf < 4; nf++)
                    mma8(d[mf][nf], ah[u][mf], bh[u][nf]);
#pragma unroll
            for (int mf = 0; mf < 4; mf++)
#pragma unroll
                for (int nf = 0; nf < 4; nf++)
                    mma8(d[mf][nf], ah[u][mf], bl[u][nf]);
#pragma unroll
            for (int mf = 0; mf < 4; mf++)
#pragma unroll
                for (int nf = 0; nf < 4; nf++)
                    mma8(d[mf][nf], al[u][mf], bh[u][nf]);
        }
        if (c + 1 < nc) sstore((c + 1) & 1);
        __syncthreads();
    }

#pragma unroll
    for (int mf = 0; mf < 4; mf++) {
        int row0 = mBase + warp_m * 64 + mf * 16 + (lane >> 2);
#pragma unroll
        for (int nf = 0; nf < 4; nf++) {
            int col = nBase + warp_n * 32 + nf * 8 + (lane & 3) * 2;
            float b0 = 0.f, b1 = 0.f;
            if (bias) {
                b0 = bias[col];
                b1 = bias[col + 1];
            }
            if (row0 < M) {
                float2 v = make_float2(d[mf][nf][0] + b0, d[mf][nf][1] + b1);
                *(float2*)(C + (size_t)row0 * ldc + col) = v;
            }
            if (row0 + 8 < M) {
                float2 v = make_float2(d[mf][nf][2] + b0, d[mf][nf][3] + b1);
                *(float2*)(C + (size_t)(row0 + 8) * ldc + col) = v;
            }
        }
    }
}

// ---------------- CSR build ---------------------------------------------------

__global__ void hist_k(const int* __restrict__ dst, int* __restrict__ deg) {
    int i = blockIdx.x * blockDim.x + threadIdx.x;
    if (i < Ee) atomicAdd(&deg[dst[i]], 1);
}

#define SCAN_T 1024
__global__ void scan_k(const int* __restrict__ deg_all,
                       int* __restrict__ base_all,
                       int* __restrict__ cur_all) {
    int z = blockIdx.x;
    const int* deg = deg_all + (size_t)z * Nn;
    int* base = base_all + (size_t)z * (Nn + 1);
    int* cur = cur_all + (size_t)z * Nn;
    __shared__ int sb[SCAN_T];
    int tid = threadIdx.x;
    const int CH = (Nn + SCAN_T - 1) / SCAN_T;
    int lo = tid * CH;
    int hi = lo + CH < Nn ? lo + CH : Nn;
    if (lo > Nn) lo = Nn;
    int s = 0;
    for (int i = lo; i < hi; i++) s += deg[i];
    sb[tid] = s;
    __syncthreads();
    for (int d = 1; d < SCAN_T; d <<= 1) {
        int v = (tid >= d) ? sb[tid - d] : 0;
        __syncthreads();
        sb[tid] += v;
        __syncthreads();
    }
    int run = sb[tid] - s;
    for (int i = lo; i < hi; i++) {
        base[i] = run;
        cur[i] = run;
        run += deg[i];
    }
    if (tid == SCAN_T - 1) base[Nn] = run;
}

__global__ void permute_k(const int* __restrict__ src,
                          const int* __restrict__ dst,
                          int* __restrict__ cur, int* __restrict__ csr) {
    int i = blockIdx.x * blockDim.x + threadIdx.x;
    if (i >= Ee) return;
    int d = dst[i];
    int p = atomicAdd(&cur[d], 1);
    csr[p] = src[i];
}

// ---- gather-mean from a strided source block --------------------------------
__global__ void __launch_bounds__(256)
gather_sum_k(const float* __restrict__ t, int ldt, const int* __restrict__ csr,
             const int* __restrict__ base, float* __restrict__ out) {
    int node = blockIdx.x * 4 + (threadIdx.x >> 6);
    int c4 = threadIdx.x & 63;
    if (node >= Nn) return;
    int s0 = __ldg(base + node);
    int s1 = __ldg(base + node + 1);
    float4 acc = make_float4(0.f, 0.f, 0.f, 0.f);
    int i = s0;
    for (; i + 4 <= s1; i += 4) {
        int a0 = __ldg(csr + i), a1 = __ldg(csr + i + 1);
        int a2 = __ldg(csr + i + 2), a3 = __ldg(csr + i + 3);
        float4 v0 = *(const float4*)(t + (size_t)a0 * ldt + c4 * 4);
        float4 v1 = *(const float4*)(t + (size_t)a1 * ldt + c4 * 4);
        float4 v2 = *(const float4*)(t + (size_t)a2 * ldt + c4 * 4);
        float4 v3 = *(const float4*)(t + (size_t)a3 * ldt + c4 * 4);
        acc.x += v0.x + v1.x + v2.x + v3.x;
        acc.y += v0.y + v1.y + v2.y + v3.y;
        acc.z += v0.z + v1.z + v2.z + v3.z;
        acc.w += v0.w + v1.w + v2.w + v3.w;
    }
    for (; i < s1; i++) {
        int a = __ldg(csr + i);
        float4 v = *(const float4*)(t + (size_t)a * ldt + c4 * 4);
        acc.x += v.x; acc.y += v.y; acc.z += v.z; acc.w += v.w;
    }
    float w = 1.0f / fmaxf((float)(s1 - s0), 1.0f);
    acc.x *= w; acc.y *= w; acc.z *= w; acc.w *= w;
    *(float4*)(out + (size_t)node * 256 + c4 * 4) = acc;
}

// ---- batched weight fusion ----
struct FuseWArgs {
    const float* Wupd[12];
    const float* W[12];
    int off[12];
    int dW[12];
    float* out[12];
};
__global__ void fuse_w_all_k(FuseWArgs a) {
    int z = blockIdx.y;
    int o = blockIdx.x;
    int k = threadIdx.x;
    int dW = a.dW[z];
    if (k >= dW) return;
    const float* wrow = a.Wupd[z] + (size_t)o * (2 * Hh) + a.off[z];
    const float* W = a.W[z];
    float s = 0.0f;
#pragma unroll 8
    for (int j = 0; j < Hh; j++) s += wrow[j] * W[(size_t)j * dW + k];
    a.out[z][(size_t)o * dW + k] = s;
}

struct FuseBArgs {
    const float* Wupd[6];
    const float* bdst[6];
    const float* bsrc[6];
    const float* bupd[6];
    float* out[6];
};
__global__ void fuse_bias_all_k(FuseBArgs a) {
    int z = blockIdx.x;
    int o = threadIdx.x;
    const float* wrow = a.Wupd[z] + (size_t)o * (2 * Hh);
    const float* bdst = a.bdst[z];
    const float* bsrc = a.bsrc[z];
    float s = a.bupd[z][o];
#pragma unroll 8
    for (int j = 0; j < Hh; j++) s += wrow[j] * bdst[j] + wrow[Hh + j] * bsrc[j];
    a.out[z][o] = s;
}

__global__ void assemble_k(const float* __restrict__ Wtmp,
                           const float* __restrict__ btmp,
                           float* __restrict__ WdA, float* __restrict__ WdA2,
                           float* __restrict__ bdA, float* __restrict__ bdA2,
                           float* __restrict__ biasB1, float* __restrict__ biasB2) {
    int z = blockIdx.y;
    int i = blockIdx.x * blockDim.x + threadIdx.x;
    const float* a = Wtmp + (size_t)(z * 2) * 65536;
    const float* b = Wtmp + (size_t)(z * 2 + 1) * 65536;
    float* W = z ? WdA2 : WdA;
    if (i < 65536) W[i] = a[i] + b[i];
    if (i < 256) {
        (z ? bdA2 : bdA)[i] = btmp[(z * 2) * 256 + i] + btmp[(z * 2 + 1) * 256 + i];
        (z ? biasB2 : biasB1)[i] = 0.f;
    }
}

// ---- BN (strided x, fused add of 1-2 aggregate buffers) ----
#define ROWS_PER_BLK 256
__global__ void col_stats3_k(const float* __restrict__ x, int ldx,
                             const float* __restrict__ a1,
                             const float* __restrict__ a2, float prescale,
                             float* __restrict__ sums) {
    int c = threadIdx.x;
    int r0 = blockIdx.x * ROWS_PER_BLK;
    int r1 = r0 + ROWS_PER_BLK;
    if (r1 > Nn) r1 = Nn;
    float s = 0.0f, s2 = 0.0f;
    for (int r = r0; r < r1; r++) {
        float v = x[(size_t)r * ldx + c] + a1[(size_t)r * 256 + c];
        if (a2) v += a2[(size_t)r * 256 + c];
        v *= prescale;
        s += v;
        s2 += v * v;
    }
    atomicAdd(&sums[c], s);
    atomicAdd(&sums[Hh + c], s2);
}

__global__ void bn_finalize_k(const float* __restrict__ sums,
                              const float* __restrict__ g,
                              const float* __restrict__ b,
                              float* __restrict__ prm) {
    int c = threadIdx.x;
    float mean = sums[c] / (float)Nn;
    float var = sums[Hh + c] / (float)Nn - mean * mean;
    float sc = g[c] * rsqrtf(var + EPSv);
    prm[c] = sc;
    prm[Hh + c] = b[c] - mean * sc;
}

__global__ void bn_apply3_k(const float* __restrict__ x, int ldx,
                            const float* __restrict__ a1,
                            const float* __restrict__ a2,
                            const float* __restrict__ prm, float prescale,
                            float* __restrict__ y) {
    int i = blockIdx.x * blockDim.x + threadIdx.x;
    if (i >= Nn * (Hh / 4)) return;
    int r = i >> 6;
    int c = (i & 63) * 4;
    float4 v = *(const float4*)(x + (size_t)r * ldx + c);
    float4 g1 = *(const float4*)(a1 + (size_t)r * 256 + c);
    if (a2) {
        float4 g2 = *(const float4*)(a2 + (size_t)r * 256 + c);
        v.x += g2.x; v.y += g2.y; v.z += g2.z; v.w += g2.w;
    }
    float4 sc = *(const float4*)(prm + c);
    float4 sh = *(const float4*)(prm + Hh + c);
    float t0 = (v.x + g1.x) * prescale * sc.x + sh.x;
    float t1 = (v.y + g1.y) * prescale * sc.y + sh.y;
    float t2 = (v.z + g1.z) * prescale * sc.z + sh.z;
    float t3 = (v.w + g1.w) * prescale * sc.w + sh.w;
    float4 r4;
    r4.x = t0 >= 0.f ? t0 : SLOPEv * t0;
    r4.y = t1 >= 0.f ? t1 : SLOPEv * t1;
    r4.z = t2 >= 0.f ? t2 : SLOPEv * t2;
    r4.w = t3 >= 0.f ? t3 : SLOPEv * t3;
    *(float4*)(y + (size_t)r * 256 + c) = r4;
}

// ---------------- host orchestration ----------------------------------------

static void run_gemm(cudaStream_t st, const float* A, const float* W,
                     const float* bias, float* C, int M, int K, int N) {
    dim3 grid((M + 127) / 128, N / 128);
    gemm_mma_k<<<grid, 256, GM_SMEM, st>>>(A, W, bias, C, M, K);
}

static void run_gather(cudaStream_t st, const float* t, int ldt, const int* csr,
                       const int* base, float* out) {
    gather_sum_k<<<(Nn + 3) / 4, 256, 0, st>>>(t, ldt, csr, base, out);
}

static void run_bn(cudaStream_t st, const float* x, int ldx, const float* a1,
                   const float* a2, float prescale, const float* g,
                   const float* b, float* y, float* stats, float* prm) {
    cudaMemsetAsync(stats, 0, 2 * Hh * sizeof(float), st);
    col_stats3_k<<<(Nn + ROWS_PER_BLK - 1) / ROWS_PER_BLK, Hh, 0, st>>>(x, ldx, a1, a2, prescale, stats);
    bn_finalize_k<<<1, Hh, 0, st>>>(stats, g, b, prm);
    bn_apply3_k<<<(Nn * (Hh / 4) + 255) / 256, 256, 0, st>>>(x, ldx, a1, a2, prm, prescale, y);
}

extern "C" void kernel_launch(void* const* d_in, const int* in_sizes, int n_in,
                              void* d_out, int out_size) {
    const float* x_A = (const float*)d_in[0];
    const float* x_B = (const float*)d_in[1];
    const int* e_ab = (const int*)d_in[2];
    const int* e_ba = (const int*)d_in[3];
    const int* e_aa = (const int*)d_in[4];
    const float* ab_Wsrc1 = (const float*)d_in[5];
    const float* ab_bsrc1 = (const float*)d_in[6];
    const float* ab_Wdst1 = (const float*)d_in[7];
    const float* ab_bdst1 = (const float*)d_in[8];
    const float* ab_Wupd1 = (const float*)d_in[9];
    const float* ab_bupd1 = (const float*)d_in[10];
    const float* ba_Wsrc1 = (const float*)d_in[11];
    const float* ba_bsrc1 = (const float*)d_in[12];
    const float* ba_Wdst1 = (const float*)d_in[13];
    const float* ba_bdst1 = (const float*)d_in[14];
    const float* ba_Wupd1 = (const float*)d_in[15];
    const float* ba_bupd1 = (const float*)d_in[16];
    const float* aa_Wsrc1 = (const float*)d_in[17];
    const float* aa_bsrc1 = (const float*)d_in[18];
    const float* aa_Wdst1 = (const float*)d_in[19];
    const float* aa_bdst1 = (const float*)d_in[20];
    const float* aa_Wupd1 = (const float*)d_in[21];
    const float* aa_bupd1 = (const float*)d_in[22];
    const float* Wsrc2 = (const float*)d_in[23];
    const float* bsrc2 = (const float*)d_in[24];
    const float* Wdst2 = (const float*)d_in[25];
    const float* bdst2 = (const float*)d_in[26];
    const float* Wupd2 = (const float*)d_in[27];
    const float* bupd2 = (const float*)d_in[28];
    const float* bn_g = (const float*)d_in[29];
    const float* bn_b = (const float*)d_in[30];
    float* out = (float*)d_out;

    float *TtA, *TB1, *TdA, *TB2, *TtA2, *TdA2, *aggr, *hA, *hB;
    float *WtA, *WB1, *WdA, *WB2, *WtA2, *WdA2;
    float *biasB1, *biasB2, *bdA, *bdA2, *Wtmp, *btmp, *stats, *prm;
    int *deg, *base, *cursor, *csr;
    cudaGetSymbolAddress((void**)&TtA, g_TtA);
    cudaGetSymbolAddress((void**)&TB1, g_TB1);
    cudaGetSymbolAddress((void**)&TdA, g_TdA);
    cudaGetSymbolAddress((void**)&TB2, g_TB2);
    cudaGetSymbolAddress((void**)&TtA2, g_TtA2);
    cudaGetSymbolAddress((void**)&TdA2, g_TdA2);
    cudaGetSymbolAddress((void**)&aggr, g_aggr);
    cudaGetSymbolAddress((void**)&hA, g_hA);
    cudaGetSymbolAddress((void**)&hB, g_hB);
    cudaGetSymbolAddress((void**)&WtA, g_WtA);
    cudaGetSymbolAddress((void**)&WB1, g_WB1);
    cudaGetSymbolAddress((void**)&WdA, g_WdA);
    cudaGetSymbolAddress((void**)&WB2, g_WB2);
    cudaGetSymbolAddress((void**)&WtA2, g_WtA2);
    cudaGetSymbolAddress((void**)&WdA2, g_WdA2);
    cudaGetSymbolAddress((void**)&biasB1, g_biasB1);
    cudaGetSymbolAddress((void**)&biasB2, g_biasB2);
    cudaGetSymbolAddress((void**)&bdA, g_bdA);
    cudaGetSymbolAddress((void**)&bdA2, g_bdA2);
    cudaGetSymbolAddress((void**)&Wtmp, g_Wtmp);
    cudaGetSymbolAddress((void**)&btmp, g_btmp);
    cudaGetSymbolAddress((void**)&stats, g_stats);
    cudaGetSymbolAddress((void**)&prm, g_prm);
    cudaGetSymbolAddress((void**)&deg, g_deg);
    cudaGetSymbolAddress((void**)&base, g_base);
    cudaGetSymbolAddress((void**)&cursor, g_cursor);
    cudaGetSymbolAddress((void**)&csr, g_csr);

#define AGGR(i) (aggr + (size_t)(i) * Nn * 256)
#define BASE(z) (base + (size_t)(z) * (Nn + 1))
#define CUR(z) (cursor + (size_t)(z) * Nn)
#define CSR(z) (csr + (size_t)(z) * Ee)
#define STATS(i) (stats + (size_t)(i) * 2 * Hh)
#define PRM(i) (prm + (size_t)(i) * 2 * Hh)

    static cudaStream_t s1 = nullptr, s2 = nullptr;
    static cudaEvent_t evFork, evFuse, evCSR, evTA, evB1, evB1g, evA1a, evA1b,
        evHB, evB2, evTA2, evA2a, evA2b, evB2g, evDone;
    if (!s1) {
        cudaStreamCreateWithFlags(&s1, cudaStreamNonBlocking);
        cudaStreamCreateWithFlags(&s2, cudaStreamNonBlocking);
        cudaEvent_t* evs[] = {&evFork, &evFuse, &evCSR, &evTA, &evB1, &evB1g,
                              &evA1a, &evA1b, &evHB, &evB2, &evTA2, &evA2a,
                              &evA2b, &evB2g, &evDone};
        for (auto e : evs) cudaEventCreateWithFlags(e, cudaEventDisableTiming);
        cudaFuncSetAttribute(gemm_mma_k,
                             cudaFuncAttributeMaxDynamicSharedMemorySize,
                             GM_SMEM);
    }
    cudaStream_t s0 = 0;

    cudaEventRecord(evFork, s0);
    cudaStreamWaitEvent(s1, evFork, 0);
    cudaStreamWaitEvent(s2, evFork, 0);

    // ===== s0: weight fusion into merged buffers ===========================
    {
        FuseWArgs fw;
        const float* wu2[3] = {Wupd2 + 0 * (size_t)Hh * 2 * Hh,
                               Wupd2 + 1 * (size_t)Hh * 2 * Hh,
                               Wupd2 + 2 * (size_t)Hh * 2 * Hh};
        fw.Wupd[0] = ab_Wupd1; fw.W[0] = ab_Wsrc1; fw.off[0] = Hh; fw.dW[0] = DAv; fw.out[0] = WtA;
        fw.Wupd[1] = aa_Wupd1; fw.W[1] = aa_Wsrc1; fw.off[1] = Hh; fw.dW[1] = DAv; fw.out[1] = WtA + 256 * 256;
        fw.Wupd[2] = ba_Wupd1; fw.W[2] = ba_Wsrc1; fw.off[2] = Hh; fw.dW[2] = DBv; fw.out[2] = WB1;
        fw.Wupd[3] = ab_Wupd1; fw.W[3] = ab_Wdst1; fw.off[3] = 0;  fw.dW[3] = DBv; fw.out[3] = WB1 + 256 * 128;
        fw.Wupd[4] = ba_Wupd1; fw.W[4] = ba_Wdst1; fw.off[4] = 0; fw.dW[4] = DAv; fw.out[4] = Wtmp + 0 * 65536;
        fw.Wupd[5] = aa_Wupd1; fw.W[5] = aa_Wdst1; fw.off[5] = 0; fw.dW[5] = DAv; fw.out[5] = Wtmp + 1 * 65536;
        fw.Wupd[6] = wu2[1]; fw.W[6] = Wsrc2 + 1 * (size_t)Hh * Hh; fw.off[6] = Hh; fw.dW[6] = Hh; fw.out[6] = WB2;
        fw.Wupd[7] = wu2[0]; fw.W[7] = Wdst2 + 0 * (size_t)Hh * Hh; fw.off[7] = 0;  fw.dW[7] = Hh; fw.out[7] = WB2 + 256 * 256;
        fw.Wupd[8] = wu2[2]; fw.W[8] = Wsrc2 + 2 * (size_t)Hh * Hh; fw.off[8] = Hh; fw.dW[8] = Hh; fw.out[8] = WtA2;
        fw.Wupd[9] = wu2[0]; fw.W[9] = Wsrc2 + 0 * (size_t)Hh * Hh; fw.off[9] = Hh; fw.dW[9] = Hh; fw.out[9] = WtA2 + 256 * 256;
        fw.Wupd[10] = wu2[1]; fw.W[10] = Wdst2 + 1 * (size_t)Hh * Hh; fw.off[10] = 0; fw.dW[10] = Hh; fw.out[10] = Wtmp + 2 * 65536;
        fw.Wupd[11] = wu2[2]; fw.W[11] = Wdst2 + 2 * (size_t)Hh * Hh; fw.off[11] = 0; fw.dW[11] = Hh; fw.out[11] = Wtmp + 3 * 65536;
        fuse_w_all_k<<<dim3(Hh, 12), 256, 0, s0>>>(fw);

        FuseBArgs fb;
        fb.Wupd[0] = ab_Wupd1; fb.bdst[0] = ab_bdst1; fb.bsrc[0] = ab_bsrc1; fb.bupd[0] = ab_bupd1; fb.out[0] = biasB1 + 256;
        fb.Wupd[1] = ba_Wupd1; fb.bdst[1] = ba_bdst1; fb.bsrc[1] = ba_bsrc1; fb.bupd[1] = ba_bupd1; fb.out[1] = btmp + 0 * 256;
        fb.Wupd[2] = aa_Wupd1; fb.bdst[2] = aa_bdst1; fb.bsrc[2] = aa_bsrc1; fb.bupd[2] = aa_bupd1; fb.out[2] = btmp + 1 * 256;
        fb.Wupd[3] = wu2[0]; fb.bdst[3] = bdst2 + 0 * Hh; fb.bsrc[3] = bsrc2 + 0 * Hh; fb.bupd[3] = bupd2 + 0 * Hh; fb.out[3] = biasB2 + 256;
        fb.Wupd[4] = wu2[1]; fb.bdst[4] = bdst2 + 1 * Hh; fb.bsrc[4] = bsrc2 + 1 * Hh; fb.bupd[4] = bupd2 + 1 * Hh; fb.out[4] = btmp + 2 * 256;
        fb.Wupd[5] = wu2[2]; fb.bdst[5] = bdst2 + 2 * Hh; fb.bsrc[5] = bsrc2 + 2 * Hh; fb.bupd[5] = bupd2 + 2 * Hh; fb.out[5] = btmp + 3 * 256;
        fuse_bias_all_k<<<6, Hh, 0, s0>>>(fb);
        assemble_k<<<dim3(256, 2), 256, 0, s0>>>(Wtmp, btmp, WdA, WdA2, bdA,
                                                 bdA2, biasB1, biasB2);
    }
    cudaEventRecord(evFuse, s0);

    // ===== s0: x_A family ==================================================
    run_gemm(s0, x_A, WtA, nullptr, TtA, Nn, DAv, 512);   // [t_ab | t_aa]
    cudaEventRecord(evTA, s0);
    run_gemm(s0, x_A, WdA, bdA, TdA, Nn, DAv, 256);       // eA

    // ===== s1: x_B family right after fuse =================================
    cudaStreamWaitEvent(s1, evFuse, 0);
    run_gemm(s1, x_B, WB1, biasB1, TB1, Nn, DBv, 512);    // [t_ba | eB]
    cudaEventRecord(evB1, s1);

    // ===== s2: CSR build (concurrent with GEMMs) ===========================
    cudaMemsetAsync(deg, 0, 3 * Nn * sizeof(int), s2);
    hist_k<<<(Ee + 255) / 256, 256, 0, s2>>>(e_ab + Ee, deg + 0 * Nn);
    hist_k<<<(Ee + 255) / 256, 256, 0, s2>>>(e_ba + Ee, deg + 1 * Nn);
    hist_k<<<(Ee + 255) / 256, 256, 0, s2>>>(e_aa + Ee, deg + 2 * Nn);
    scan_k<<<3, SCAN_T, 0, s2>>>(deg, base, cursor);
    permute_k<<<(Ee + 255) / 256, 256, 0, s2>>>(e_ab, e_ab + Ee, CUR(0), CSR(0));
    permute_k<<<(Ee + 255) / 256, 256, 0, s2>>>(e_ba, e_ba + Ee, CUR(1), CSR(1));
    permute_k<<<(Ee + 255) / 256, 256, 0, s2>>>(e_aa, e_aa + Ee, CUR(2), CSR(2));
    cudaEventRecord(evCSR, s2);

    // ===== layer-1 gathers (R14 placement) =================================
    cudaStreamWaitEvent(s1, evCSR, 0);
    run_gather(s1, TB1, 512, CSR(1), BASE(1), AGGR(1));   // aA1a (t_ba)
    cudaEventRecord(evA1a, s1);
    cudaStreamWaitEvent(s2, evTA, 0);
    run_gather(s2, TtA, 512, CSR(0), BASE(0), AGGR(0));   // aB1 (t_ab)
    cudaEventRecord(evB1g, s2);
    cudaStreamWaitEvent(s1, evTA, 0);
    run_gather(s1, TtA + 256, 512, CSR(2), BASE(2), AGGR(2));  // aA1b (t_aa)
    cudaEventRecord(evA1b, s1);

    // ===== s0: BN_B1 -> hB; s1: hB family (R14 placement) ==================
    cudaStreamWaitEvent(s0, evB1, 0);
    cudaStreamWaitEvent(s0, evB1g, 0);
    run_bn(s0, TB1 + 256, 512, AGGR(0), nullptr, 1.0f, bn_g + 1 * Hh,
           bn_b + 1 * Hh, hB, STATS(0), PRM(0));
    cudaEventRecord(evHB, s0);
    cudaStreamWaitEvent(s1, evHB, 0);
    run_gemm(s1, hB, WB2, biasB2, TB2, Nn, Hh, 512);      // [t2_ba | eB2]
    cudaEventRecord(evB2, s1);

    // ===== s0: BN_A1 -> hA; hA family ======================================
    cudaStreamWaitEvent(s0, evA1a, 0);
    cudaStreamWaitEvent(s0, evA1b, 0);
    run_bn(s0, TdA, 256, AGGR(1), AGGR(2), 0.5f, bn_g + 0 * Hh, bn_b + 0 * Hh,
           hA, STATS(1), PRM(1));
    run_gemm(s0, hA, WtA2, nullptr, TtA2, Nn, Hh, 512);   // [t2_aa | t2_ab]
    cudaEventRecord(evTA2, s0);
    run_gemm(s0, hA, WdA2, bdA2, TdA2, Nn, Hh, 256);      // eA2

    // ===== layer-2 gathers (R14 placement) =================================
    cudaStreamWaitEvent(s2, evB2, 0);
    run_gather(s2, TB2, 512, CSR(1), BASE(1), AGGR(3));   // aA2a (t2_ba)
    cudaEventRecord(evA2a, s2);
    cudaStreamWaitEvent(s1, evTA2, 0);
    run_gather(s1, TtA2, 512, CSR(2), BASE(2), AGGR(4));  // aA2b (t2_aa)
    cudaEventRecord(evA2b, s1);
    cudaStreamWaitEvent(s2, evTA2, 0);
    run_gather(s2, TtA2 + 256, 512, CSR(0), BASE(0), AGGR(5));  // aB2 (t2_ab)
    cudaEventRecord(evB2g, s2);

    // ===== output BNs: outA on s0 || outB on s1 (tail-only parallelism) ====
    cudaStreamWaitEvent(s0, evA2a, 0);
    cudaStreamWaitEvent(s0, evA2b, 0);
    run_bn(s0, TdA2, 256, AGGR(3), AGGR(4), 0.5f, bn_g + 2 * Hh, bn_b + 2 * Hh,
           out, STATS(0), PRM(0));
    cudaStreamWaitEvent(s1, evB2, 0);
    cudaStreamWaitEvent(s1, evB2g, 0);
    run_bn(s1, TB2 + 256, 512, AGGR(5), nullptr, 1.0f, bn_g + 3 * Hh,
           bn_b + 3 * Hh, out + (size_t)Nn * Hh, STATS(1), PRM(1));
    cudaEventRecord(evDone, s1);
    cudaStreamWaitEvent(s0, evDone, 0);
}